// round 14
// baseline (speedup 1.0000x reference)
#include <cuda_runtime.h>
#include <math.h>

// Problem-size constants (fixed by the dataset).
constexpr int MAX_N  = 100000;
constexpr int MAX_E  = 1600000;
constexpr int SCAN_B = 1024;
constexpr int NSCAN  = (MAX_N + SCAN_B - 1) / SCAN_B;  // 98

// ---------------- device scratch (static: no allocation allowed) -----------
// Zero-in/zero-out protocol: deg/loopsum/cursor/asrc2/adst2 are statically
// zero at module load; each kernel_launch call re-zeroes them in the agg
// epilogues, so every call starts from zeros. Deterministic across replays.
__device__ int   s_deg[MAX_N];
__device__ float s_loopsum[MAX_N];
__device__ float s_loopattr[MAX_N];
__device__ int   s_rowptr[MAX_N + 1];
__device__ int   s_cursor[MAX_N];
__device__ int   s_incl[MAX_N];
__device__ int   s_bsum[NSCAN];
__device__ __align__(16) int2  s_csr[MAX_E];          // (src, attr-bits)
__device__ __align__(16) float s_h1 [(size_t)MAX_N * 128];
__device__ __align__(16) float s_h1a[(size_t)MAX_N * 128];
__device__ __align__(16) float s_h2 [(size_t)MAX_N * 64];
__device__ __align__(16) float s_asrc1[MAX_N * 4];
__device__ __align__(16) float s_adst1[MAX_N * 4];
__device__ float s_asrc2[MAX_N];
__device__ float s_adst2[MAX_N];
__device__ float s_wedot[8];   // [0..3] layer1 per-head, [4] layer2

// ---- bf16 as raw bits ----------------------------------------------------
__device__ __forceinline__ unsigned to_bf(float f) {
    unsigned b = __float_as_uint(f);
    return (b + 0x7FFFu + ((b >> 16) & 1u)) >> 16;   // RNE
}
__device__ __forceinline__ float from_bf(unsigned u) {
    return __uint_as_float(u << 16);
}

// ==================== tensor-core GEMM (bf16x3 split) ========================
__device__ __forceinline__ void mma_bf16(float* c, const unsigned* a, const unsigned* b) {
    asm volatile(
        "mma.sync.aligned.m16n8k16.row.col.f32.bf16.bf16.f32 "
        "{%0,%1,%2,%3}, {%4,%5,%6,%7}, {%8,%9}, {%0,%1,%2,%3};\n"
        : "+f"(c[0]), "+f"(c[1]), "+f"(c[2]), "+f"(c[3])
        : "r"(a[0]), "r"(a[1]), "r"(a[2]), "r"(a[3]), "r"(b[0]), "r"(b[1]));
}

__device__ __forceinline__ void ldsm4(unsigned* d, const unsigned short* p) {
    unsigned addr = (unsigned)__cvta_generic_to_shared(p);
    asm volatile("ldmatrix.sync.aligned.m8n8.x4.shared.b16 {%0,%1,%2,%3}, [%4];"
                 : "=r"(d[0]), "=r"(d[1]), "=r"(d[2]), "=r"(d[3]) : "r"(addr));
}

__device__ __forceinline__ void ldsm4t(unsigned* d, const unsigned short* p) {
    unsigned addr = (unsigned)__cvta_generic_to_shared(p);
    asm volatile("ldmatrix.sync.aligned.m8n8.x4.trans.shared.b16 {%0,%1,%2,%3}, [%4];"
                 : "=r"(d[0]), "=r"(d[1]), "=r"(d[2]), "=r"(d[3]) : "r"(addr));
}

template <int BN, int BNP, bool L2MODE, int LAYER>
__global__ void __launch_bounds__(256) kg_mma(const float* __restrict__ Af32,
                                              const float* __restrict__ Bf32,
                                              const float* __restrict__ avs,
                                              const float* __restrict__ avd,
                                              int M) {
    constexpr int BM = 128;
    constexpr int AP = 40;             // A smem row stride (80B, conflict-free)
    constexpr int NT = BN / 16;
    constexpr int NH = (LAYER == 1) ? 2 : 1;

    const float* Asrc = L2MODE ? (const float*)s_h1a : Af32;
    float* C = L2MODE ? (float*)s_h2 : (float*)s_h1;

    extern __shared__ __align__(16) char smem_raw[];
    unsigned short* Bhi = (unsigned short*)smem_raw;
    unsigned short* Blo = Bhi + 128 * BNP;
    unsigned short* Ahi = Blo + 128 * BNP;
    unsigned short* Alo = Ahi + BM * AP;

    int tid = threadIdx.x;
    int lane = tid & 31, wid = tid >> 5;
    int wm = (wid & 3) * 32;
    int wn = (wid >> 2) * (BN / 2);
    int blockRow = blockIdx.x * BM;

    // B -> hi/lo bf16 smem, once per block
    for (int i = tid; i < 128 * BN / 2; i += 256) {
        int kr = i / (BN / 2);
        int cc = (i % (BN / 2)) * 2;
        float bx = Bf32[(size_t)kr * BN + cc];
        float by = Bf32[(size_t)kr * BN + cc + 1];
        unsigned hx = to_bf(bx);
        unsigned hy = to_bf(by);
        unsigned lx = to_bf(bx - from_bf(hx));
        unsigned ly = to_bf(by - from_bf(hy));
        *(unsigned*)(Bhi + (size_t)kr * BNP + cc) = hx | (hy << 16);
        *(unsigned*)(Blo + (size_t)kr * BNP + cc) = lx | (ly << 16);
    }

    float acc[2][NT][4];
#pragma unroll
    for (int mt = 0; mt < 2; mt++)
#pragma unroll
        for (int nt = 0; nt < NT; nt++)
#pragma unroll
            for (int j = 0; j < 4; j++) acc[mt][nt][j] = 0.f;

    int ar = tid >> 1, ahalf = tid & 1;
    int agr = blockRow + ar;
    bool aval = agr < M;

    int lrow = lane & 15;
    int lcol8 = (lane >> 4) << 3;

#pragma unroll
    for (int kt = 0; kt < 4; kt++) {
        int k0 = kt * 32;
        {
            const float* ap = Asrc + (size_t)agr * 128 + k0 + ahalf * 16;
            unsigned short* dsth = Ahi + ar * AP + ahalf * 16;
            unsigned short* dstl = Alo + ar * AP + ahalf * 16;
#pragma unroll
            for (int j = 0; j < 16; j += 4) {
                float4 t;
                if (aval) t = *(const float4*)(ap + j);
                else t = make_float4(0.f, 0.f, 0.f, 0.f);
                unsigned h0 = to_bf(t.x);
                unsigned h1 = to_bf(t.y);
                unsigned h2 = to_bf(t.z);
                unsigned h3 = to_bf(t.w);
                *(unsigned*)(dsth + j)     = h0 | (h1 << 16);
                *(unsigned*)(dsth + j + 2) = h2 | (h3 << 16);
                unsigned l0 = to_bf(t.x - from_bf(h0));
                unsigned l1 = to_bf(t.y - from_bf(h1));
                unsigned l2 = to_bf(t.z - from_bf(h2));
                unsigned l3 = to_bf(t.w - from_bf(h3));
                *(unsigned*)(dstl + j)     = l0 | (l1 << 16);
                *(unsigned*)(dstl + j + 2) = l2 | (l3 << 16);
            }
        }
        __syncthreads();

#pragma unroll
        for (int ks = 0; ks < 2; ks++) {
            int kc = ks * 16;
            unsigned afh[2][4], afl[2][4];
#pragma unroll
            for (int mt = 0; mt < 2; mt++) {
                ldsm4(afh[mt], Ahi + (wm + mt * 16 + lrow) * AP + kc + lcol8);
                ldsm4(afl[mt], Alo + (wm + mt * 16 + lrow) * AP + kc + lcol8);
            }
            unsigned bfh[NT][2], bfl[NT][2];
            int krow = k0 + kc + lrow;
#pragma unroll
            for (int np = 0; np < NT / 2; np++) {
                unsigned t4[4];
                ldsm4t(t4, Bhi + (size_t)krow * BNP + wn + np * 16 + lcol8);
                bfh[2 * np][0] = t4[0]; bfh[2 * np][1] = t4[1];
                bfh[2 * np + 1][0] = t4[2]; bfh[2 * np + 1][1] = t4[3];
                ldsm4t(t4, Blo + (size_t)krow * BNP + wn + np * 16 + lcol8);
                bfl[2 * np][0] = t4[0]; bfl[2 * np][1] = t4[1];
                bfl[2 * np + 1][0] = t4[2]; bfl[2 * np + 1][1] = t4[3];
            }
#pragma unroll
            for (int mt = 0; mt < 2; mt++)
#pragma unroll
                for (int nt = 0; nt < NT; nt++) {
                    mma_bf16(acc[mt][nt], afh[mt], bfh[nt]);
                    mma_bf16(acc[mt][nt], afh[mt], bfl[nt]);
                    mma_bf16(acc[mt][nt], afl[mt], bfh[nt]);
                }
        }
        __syncthreads();
    }

    // epilogue: store C + fused attention dots
    float ps[2][2][NH][2];
#pragma unroll
    for (int mt = 0; mt < 2; mt++)
#pragma unroll
        for (int rh = 0; rh < 2; rh++)
#pragma unroll
            for (int ih = 0; ih < NH; ih++) {
                ps[mt][rh][ih][0] = 0.f;
                ps[mt][rh][ih][1] = 0.f;
            }

#pragma unroll
    for (int mt = 0; mt < 2; mt++) {
        int row = blockRow + wm + mt * 16 + (lane >> 2);
#pragma unroll
        for (int nt = 0; nt < NT; nt++) {
            int col = wn + nt * 8 + (lane & 3) * 2;
            float c0 = acc[mt][nt][0], c1 = acc[mt][nt][1];
            float c2 = acc[mt][nt][2], c3 = acc[mt][nt][3];
            if (row < M)
                *(float2*)(C + (size_t)row * BN + col) = make_float2(c0, c1);
            if (row + 8 < M)
                *(float2*)(C + (size_t)(row + 8) * BN + col) = make_float2(c2, c3);
            float w0 = avs[col], w1 = avs[col + 1];
            float z0 = avd[col], z1 = avd[col + 1];
            int ih = (LAYER == 1) ? (nt >> 2) : 0;
            ps[mt][0][ih][0] += c0 * w0 + c1 * w1;
            ps[mt][0][ih][1] += c0 * z0 + c1 * z1;
            ps[mt][1][ih][0] += c2 * w0 + c3 * w1;
            ps[mt][1][ih][1] += c2 * z0 + c3 * z1;
        }
    }
#pragma unroll
    for (int mt = 0; mt < 2; mt++)
#pragma unroll
        for (int rh = 0; rh < 2; rh++)
#pragma unroll
            for (int ih = 0; ih < NH; ih++)
#pragma unroll
                for (int sd = 0; sd < 2; sd++) {
                    float v = ps[mt][rh][ih][sd];
                    v += __shfl_xor_sync(0xffffffffu, v, 1);
                    v += __shfl_xor_sync(0xffffffffu, v, 2);
                    ps[mt][rh][ih][sd] = v;
                }
    if ((lane & 3) == 0) {
#pragma unroll
        for (int mt = 0; mt < 2; mt++)
#pragma unroll
            for (int rh = 0; rh < 2; rh++) {
                int row = blockRow + wm + mt * 16 + (lane >> 2) + rh * 8;
                if (row < M) {
                    if (LAYER == 1) {
                        int bh = wn >> 5;
#pragma unroll
                        for (int ih = 0; ih < NH; ih++) {
                            s_asrc1[row * 4 + bh + ih] = ps[mt][rh][ih][0];
                            s_adst1[row * 4 + bh + ih] = ps[mt][rh][ih][1];
                        }
                    } else {
                        atomicAdd(&s_asrc2[row], ps[mt][rh][0][0]);
                        atomicAdd(&s_adst2[row], ps[mt][rh][0][1]);
                    }
                }
            }
    }
}

// ---------------- degree count + self-loop attr sum -------------------------
__global__ void kg_count(const int* __restrict__ dst, const float* __restrict__ attr,
                         int E) {
    int e = blockIdx.x * blockDim.x + threadIdx.x;
    if (e >= E) return;
    int d = __ldg(dst + e);
    atomicAdd(&s_deg[d], 1);
    atomicAdd(&s_loopsum[d], __ldg(attr + e));
}

// ---------------- scan phase 1: per-block inclusive scan ---------------------
__global__ void kg_scan1(int n) {
    int b = blockIdx.x, t = threadIdx.x, lane = t & 31, wid = t >> 5;
    int i = b * SCAN_B + t;
    int v = (i < n) ? s_deg[i] : 0;
#pragma unroll
    for (int o = 1; o < 32; o <<= 1) {
        int u = __shfl_up_sync(0xffffffffu, v, o);
        if (lane >= o) v += u;
    }
    __shared__ int ws[32];
    if (lane == 31) ws[wid] = v;
    __syncthreads();
    if (wid == 0) {
        int w = ws[lane];
#pragma unroll
        for (int o = 1; o < 32; o <<= 1) {
            int u = __shfl_up_sync(0xffffffffu, w, o);
            if (lane >= o) w += u;
        }
        ws[lane] = w;
    }
    __syncthreads();
    if (wid > 0) v += ws[wid - 1];
    if (i < n) s_incl[i] = v;
    if (t == SCAN_B - 1) s_bsum[b] = v;
}

// ---------------- scan phase 2 (merged): offsets + loopattr + wedot ----------
__global__ void kg_scanB(const float* __restrict__ We1, const float* __restrict__ ae1,
                         const float* __restrict__ We2, const float* __restrict__ ae2,
                         int n) {
    int b = blockIdx.x, t = threadIdx.x;
    __shared__ int soff;
    if (t == 0) {
        int acc = 0;
        for (int j = 0; j < b; j++) acc += s_bsum[j];
        soff = acc;
        if (b == 0) s_rowptr[0] = 0;
    }
    __syncthreads();
    int off = soff;
    for (int k = t; k < SCAN_B; k += blockDim.x) {
        int i = b * SCAN_B + k;
        if (i < n) {
            s_rowptr[i + 1] = s_incl[i] + off;
            int d = s_deg[i];
            s_loopattr[i] = s_loopsum[i] / (float)max(d, 1);
        }
    }
    if (b == 0 && t < 32) {
        int l = t;
#pragma unroll
        for (int h = 0; h < 4; h++) {
            float v = We1[h * 32 + l] * ae1[h * 32 + l];
#pragma unroll
            for (int o = 16; o; o >>= 1) v += __shfl_xor_sync(0xffffffffu, v, o);
            if (l == 0) s_wedot[h] = v;
        }
        float v2 = We2[l] * ae2[l] + We2[l + 32] * ae2[l + 32];
#pragma unroll
        for (int o = 16; o; o >>= 1) v2 += __shfl_xor_sync(0xffffffffu, v2, o);
        if (l == 0) s_wedot[4] = v2;
    }
}

// ---------------- CSR fill ---------------------------------------------------
__global__ void kg_fill(const int* __restrict__ src, const int* __restrict__ dst,
                        const float* __restrict__ attr, int E) {
    int e = blockIdx.x * blockDim.x + threadIdx.x;
    if (e >= E) return;
    int d = __ldg(dst + e);
    int p = atomicAdd(&s_cursor[d], 1);
    s_csr[s_rowptr[d] + p] = make_int2(__ldg(src + e), __float_as_int(__ldg(attr + e)));
}

// ---------------- layer-1 aggregation (softmax gather, no online max) --------
__global__ void kg_agg1(const float* __restrict__ b1, int n) {
    int gw = (blockIdx.x * blockDim.x + threadIdx.x) >> 5;
    if (gw >= n) return;
    int lane = threadIdx.x & 31;
    int hh = lane >> 3;

    int beg = s_rowptr[gw], end = s_rowptr[gw + 1];
    float ad = s_adst1[gw * 4 + hh];
    float wd = s_wedot[hh];

    float s, ax, ay, az, aw;
    {
        float alpha = s_asrc1[gw * 4 + hh] + ad + s_loopattr[gw] * wd;
        alpha = (alpha > 0.f) ? alpha : 0.2f * alpha;
        float w = __expf(alpha);
        s = w;
        float4 hv = *(const float4*)(s_h1 + (size_t)gw * 128 + lane * 4);
        ax = w * hv.x; ay = w * hv.y; az = w * hv.z; aw = w * hv.w;
    }

#pragma unroll 4
    for (int i = beg; i < end; i++) {
        int2 c = s_csr[i];
        float as = s_asrc1[c.x * 4 + hh];
        float4 hv = *(const float4*)(s_h1 + (size_t)c.x * 128 + lane * 4);
        float alpha = as + ad + __int_as_float(c.y) * wd;
        alpha = (alpha > 0.f) ? alpha : 0.2f * alpha;
        float w = __expf(alpha);
        s += w;
        ax = fmaf(w, hv.x, ax); ay = fmaf(w, hv.y, ay);
        az = fmaf(w, hv.z, az); aw = fmaf(w, hv.w, aw);
    }

    float inv = 1.f / (s + 1e-16f);
    float4 bv = *(const float4*)(b1 + lane * 4);
    float v0 = ax * inv + bv.x;
    float v1 = ay * inv + bv.y;
    float v2 = az * inv + bv.z;
    float v3 = aw * inv + bv.w;
    v0 = (v0 > 0.f) ? v0 : expm1f(v0);
    v1 = (v1 > 0.f) ? v1 : expm1f(v1);
    v2 = (v2 > 0.f) ? v2 : expm1f(v2);
    v3 = (v3 > 0.f) ? v3 : expm1f(v3);
    *(float4*)(s_h1a + (size_t)gw * 128 + lane * 4) = make_float4(v0, v1, v2, v3);

    if (lane == 0) {
        s_asrc2[gw] = 0.f;   // must be zero before GEMM2's atomic accumulation
        s_adst2[gw] = 0.f;
    }
}

// ---------------- layer-2 aggregation + final FC (fused) ---------------------
__global__ void kg_agg2(const float* __restrict__ b2, const float* __restrict__ fcW,
                        const float* __restrict__ fcb, float* __restrict__ out, int n) {
    int gw = (blockIdx.x * blockDim.x + threadIdx.x) >> 5;
    if (gw >= n) return;
    int lane = threadIdx.x & 31;

    int beg = s_rowptr[gw], end = s_rowptr[gw + 1];
    float ad = s_adst2[gw];
    float wd = s_wedot[4];

    float s, a0, a1;
    {
        float alpha = s_asrc2[gw] + ad + s_loopattr[gw] * wd;
        alpha = (alpha > 0.f) ? alpha : 0.2f * alpha;
        float w = __expf(alpha);
        s = w;
        float2 hv = *(const float2*)(s_h2 + (size_t)gw * 64 + lane * 2);
        a0 = w * hv.x; a1 = w * hv.y;
    }

#pragma unroll 4
    for (int i = beg; i < end; i++) {
        int2 c = s_csr[i];
        float as = s_asrc2[c.x];
        float2 hv = *(const float2*)(s_h2 + (size_t)c.x * 64 + lane * 2);
        float alpha = as + ad + __int_as_float(c.y) * wd;
        alpha = (alpha > 0.f) ? alpha : 0.2f * alpha;
        float w = __expf(alpha);
        s += w;
        a0 = fmaf(w, hv.x, a0); a1 = fmaf(w, hv.y, a1);
    }

    float inv = 1.f / (s + 1e-16f);
    float v0 = a0 * inv + b2[lane * 2];
    float v1 = a1 * inv + b2[lane * 2 + 1];
    float p = v0 * fcW[lane * 2] + v1 * fcW[lane * 2 + 1];
#pragma unroll
    for (int o = 16; o; o >>= 1) p += __shfl_xor_sync(0xffffffffu, p, o);
    if (lane == 0) {
        out[gw] = p + fcb[0];
        // re-zero for the next call (nothing later in THIS call reads these)
        s_deg[gw] = 0;
        s_loopsum[gw] = 0.f;
        s_cursor[gw] = 0;
    }
}

// ---------------- launch -----------------------------------------------------
extern "C" void kernel_launch(void* const* d_in, const int* in_sizes, int n_in,
                              void* d_out, int out_size) {
    const float* x    = (const float*)d_in[0];
    const int*   ei   = (const int*)d_in[1];
    const float* eatt = (const float*)d_in[2];
    const float* W1   = (const float*)d_in[3];
    const float* as1  = (const float*)d_in[4];
    const float* ad1  = (const float*)d_in[5];
    const float* We1  = (const float*)d_in[6];
    const float* ae1  = (const float*)d_in[7];
    const float* b1   = (const float*)d_in[8];
    const float* W2   = (const float*)d_in[9];
    const float* as2  = (const float*)d_in[10];
    const float* ad2  = (const float*)d_in[11];
    const float* We2  = (const float*)d_in[12];
    const float* ae2  = (const float*)d_in[13];
    const float* b2   = (const float*)d_in[14];
    const float* fcW  = (const float*)d_in[15];
    const float* fcb  = (const float*)d_in[16];
    float* out = (float*)d_out;

    int N = in_sizes[0] / 128;
    int E = in_sizes[1] / 2;
    const int* src = ei;
    const int* dst = ei + E;

    int eb = (E + 255) / 256;
    int nbscan = (N + SCAN_B - 1) / SCAN_B;
    int nwb = (N + 7) / 8;

    constexpr int SMEM1 = (2 * 128 * 136 + 2 * 128 * 40) * 2;  // 90112 B
    constexpr int SMEM2 = (2 * 128 * 72 + 2 * 128 * 40) * 2;   // 57344 B
    cudaFuncSetAttribute(kg_mma<128, 136, false, 1>,
                         cudaFuncAttributeMaxDynamicSharedMemorySize, SMEM1);
    cudaFuncSetAttribute(kg_mma<64, 72, true, 2>,
                         cudaFuncAttributeMaxDynamicSharedMemorySize, SMEM2);

    kg_count<<<eb, 256>>>(dst, eatt, E);
    kg_scan1<<<nbscan, SCAN_B>>>(N);
    kg_scanB<<<nbscan, 256>>>(We1, ae1, We2, ae2, N);
    kg_fill<<<eb, 256>>>(src, dst, eatt, E);

    kg_mma<128, 136, false, 1><<<(N + 127) / 128, 256, SMEM1>>>(x, W1, as1, ad1, N);
    kg_agg1<<<nwb, 256>>>(b1, N);

    kg_mma<64, 72, true, 2><<<(N + 127) / 128, 256, SMEM2>>>(nullptr, W2, as2, ad2, N);
    kg_agg2<<<nwb, 256>>>(b2, fcW, fcb, out, N);
}

// round 15
// speedup vs baseline: 1.0716x; 1.0716x over previous
#include <cuda_runtime.h>
#include <math.h>

// Problem-size constants (fixed by the dataset).
constexpr int MAX_N  = 100000;
constexpr int MAX_E  = 1600000;
constexpr int SCAN_B = 1024;
constexpr int NSCAN  = (MAX_N + SCAN_B - 1) / SCAN_B;  // 98

// ---------------- device scratch (static: no allocation allowed) -----------
__device__ int   g_deg[MAX_N];
__device__ float g_loopsum[MAX_N];
__device__ float g_loopattr[MAX_N];
__device__ int   g_rowptr[MAX_N + 1];
__device__ int   g_incl[MAX_N];
__device__ int   g_bsum[NSCAN];
__device__ int   g_slot[MAX_E];                       // per-edge slot from count
__device__ __align__(16) int2  g_csr[MAX_E];          // (src, attr-bits)
__device__ __align__(16) float g_h1 [(size_t)MAX_N * 128];
__device__ __align__(16) float g_h1a[(size_t)MAX_N * 128];
__device__ __align__(16) float g_h2 [(size_t)MAX_N * 64];
__device__ __align__(16) float g_asrc1[MAX_N * 4];
__device__ __align__(16) float g_adst1[MAX_N * 4];
__device__ float g_asrc2[MAX_N];
__device__ float g_adst2[MAX_N];
__device__ float g_wedot[8];   // [0..3] layer1 per-head, [4] layer2

// ---- bf16 as raw bits: no cuda_bf16.h anywhere --------------------------
__device__ __forceinline__ unsigned f2bf(float f) {
    unsigned b = __float_as_uint(f);
    return (b + 0x7FFFu + ((b >> 16) & 1u)) >> 16;   // round-to-nearest-even
}
__device__ __forceinline__ float bf2f(unsigned u) {
    return __uint_as_float(u << 16);
}

// ---------------- init counters + wedot precompute (merged) ------------------
__global__ void k_init(const float* __restrict__ We1, const float* __restrict__ ae1,
                       const float* __restrict__ We2, const float* __restrict__ ae2,
                       int n) {
    int i = blockIdx.x * blockDim.x + threadIdx.x;
    int stride = gridDim.x * blockDim.x;
    for (; i < n; i += stride) {
        g_deg[i] = 0;
        g_loopsum[i] = 0.f;
        g_asrc2[i] = 0.f;   // gemm2 epilogue accumulates via atomicAdd
        g_adst2[i] = 0.f;
    }
    if (blockIdx.x == 0 && threadIdx.x < 32) {
        int l = threadIdx.x;
#pragma unroll
        for (int h = 0; h < 4; h++) {
            float v = We1[h * 32 + l] * ae1[h * 32 + l];
#pragma unroll
            for (int o = 16; o; o >>= 1) v += __shfl_xor_sync(0xffffffffu, v, o);
            if (l == 0) g_wedot[h] = v;
        }
        float v2 = We2[l] * ae2[l] + We2[l + 32] * ae2[l + 32];
#pragma unroll
        for (int o = 16; o; o >>= 1) v2 += __shfl_xor_sync(0xffffffffu, v2, o);
        if (l == 0) g_wedot[4] = v2;
    }
}

// ---------------- degree count + self-loop attr sum + slot assignment -------
__global__ void k_count(const int* __restrict__ dst, const float* __restrict__ attr,
                        int E) {
    int e = blockIdx.x * blockDim.x + threadIdx.x;
    if (e >= E) return;
    int d = dst[e];
    g_slot[e] = atomicAdd(&g_deg[d], 1);   // slot doubles as degree counter
    atomicAdd(&g_loopsum[d], attr[e]);
}

// ---------------- 3-phase exclusive scan of g_deg -> g_rowptr ---------------
__global__ void k_scan1(int n) {
    int b = blockIdx.x, t = threadIdx.x, lane = t & 31, wid = t >> 5;
    int i = b * SCAN_B + t;
    int v = (i < n) ? g_deg[i] : 0;
#pragma unroll
    for (int o = 1; o < 32; o <<= 1) {
        int u = __shfl_up_sync(0xffffffffu, v, o);
        if (lane >= o) v += u;
    }
    __shared__ int ws[32];
    if (lane == 31) ws[wid] = v;
    __syncthreads();
    if (wid == 0) {
        int w = ws[lane];
#pragma unroll
        for (int o = 1; o < 32; o <<= 1) {
            int u = __shfl_up_sync(0xffffffffu, w, o);
            if (lane >= o) w += u;
        }
        ws[lane] = w;
    }
    __syncthreads();
    if (wid > 0) v += ws[wid - 1];
    if (i < n) g_incl[i] = v;
    if (t == SCAN_B - 1) g_bsum[b] = v;
}

__global__ void k_scan2(int nb) {
    __shared__ int sh[128];
    int t = threadIdx.x;
    sh[t] = (t < nb) ? g_bsum[t] : 0;
    __syncthreads();
    for (int o = 1; o < 128; o <<= 1) {
        int u = (t >= o) ? sh[t - o] : 0;
        __syncthreads();
        sh[t] += u;
        __syncthreads();
    }
    if (t < nb) g_bsum[t] = (t > 0) ? sh[t - 1] : 0;  // exclusive block offsets
}

__global__ void k_scan3(int n) {
    int i = blockIdx.x * blockDim.x + threadIdx.x;
    if (i >= n) return;
    g_rowptr[i + 1] = g_incl[i] + g_bsum[i / SCAN_B];
    if (i == 0) g_rowptr[0] = 0;
    int d = g_deg[i];
    g_loopattr[i] = g_loopsum[i] / (float)max(d, 1);
}

// ---------------- CSR fill: NO atomics (slot precomputed in k_count) ---------
__global__ void k_fill(const int* __restrict__ src, const int* __restrict__ dst,
                       const float* __restrict__ attr, int E) {
    int e = blockIdx.x * blockDim.x + threadIdx.x;
    if (e >= E) return;
    int d = dst[e];
    int idx = g_rowptr[d] + g_slot[e];
    g_csr[idx] = make_int2(src[e], __float_as_int(attr[e]));
}

// ==================== tensor-core GEMM (bf16x3 split) ========================
// C[M,BN] = A[M,128] * B[128,BN], fp32-accurate via hi/lo bf16 split:
// A*B ~= Ahi*Bhi + Ahi*Blo + Alo*Bhi  (lo*lo term ~eps^2 dropped).
// BM=128 rows/block, 8 warps (4 along M x 2 along N), warp tile 32 x BN/2.
// Epilogue fuses the per-row attention dot-products (a_src, a_dst).

__device__ __forceinline__ void mma_bf16(float* c, const unsigned* a, const unsigned* b) {
    asm volatile(
        "mma.sync.aligned.m16n8k16.row.col.f32.bf16.bf16.f32 "
        "{%0,%1,%2,%3}, {%4,%5,%6,%7}, {%8,%9}, {%0,%1,%2,%3};\n"
        : "+f"(c[0]), "+f"(c[1]), "+f"(c[2]), "+f"(c[3])
        : "r"(a[0]), "r"(a[1]), "r"(a[2]), "r"(a[3]), "r"(b[0]), "r"(b[1]));
}

__device__ __forceinline__ void ldsm_x4(unsigned* d, const unsigned short* p) {
    unsigned addr = (unsigned)__cvta_generic_to_shared(p);
    asm volatile("ldmatrix.sync.aligned.m8n8.x4.shared.b16 {%0,%1,%2,%3}, [%4];"
                 : "=r"(d[0]), "=r"(d[1]), "=r"(d[2]), "=r"(d[3]) : "r"(addr));
}

__device__ __forceinline__ void ldsm_x4t(unsigned* d, const unsigned short* p) {
    unsigned addr = (unsigned)__cvta_generic_to_shared(p);
    asm volatile("ldmatrix.sync.aligned.m8n8.x4.trans.shared.b16 {%0,%1,%2,%3}, [%4];"
                 : "=r"(d[0]), "=r"(d[1]), "=r"(d[2]), "=r"(d[3]) : "r"(addr));
}

template <int BN, int BNP, bool L2MODE, int LAYER>
__global__ void __launch_bounds__(256) k_gemm_mma(const float* __restrict__ Af32,
                                                  const float* __restrict__ Bf32,
                                                  const float* __restrict__ avs,
                                                  const float* __restrict__ avd,
                                                  int M) {
    constexpr int BM = 128;
    constexpr int AP = 40;             // A smem row stride (80B, conflict-free)
    constexpr int NT = BN / 16;        // n8 tiles per warp (8 for BN=128, 4 for 64)
    constexpr int NH = (LAYER == 1) ? 2 : 1;   // heads per warp span

    const float* Asrc = L2MODE ? (const float*)g_h1a : Af32;
    float* C = L2MODE ? (float*)g_h2 : (float*)g_h1;

    extern __shared__ __align__(16) char smem_raw[];
    unsigned short* Bhi = (unsigned short*)smem_raw;
    unsigned short* Blo = Bhi + 128 * BNP;
    unsigned short* Ahi = Blo + 128 * BNP;
    unsigned short* Alo = Ahi + BM * AP;

    int tid = threadIdx.x;
    int lane = tid & 31, wid = tid >> 5;
    int wm = (wid & 3) * 32;           // warp M base within block
    int wn = (wid >> 2) * (BN / 2);    // warp N base
    int blockRow = blockIdx.x * BM;

    // ---- load + convert B (fp32 -> hi/lo bf16 bits) once ----
    for (int i = tid; i < 128 * BN / 2; i += 256) {
        int kr = i / (BN / 2);
        int cc = (i % (BN / 2)) * 2;
        float bx = Bf32[(size_t)kr * BN + cc];
        float by = Bf32[(size_t)kr * BN + cc + 1];
        unsigned hx = f2bf(bx);
        unsigned hy = f2bf(by);
        unsigned lx = f2bf(bx - bf2f(hx));
        unsigned ly = f2bf(by - bf2f(hy));
        *(unsigned*)(Bhi + (size_t)kr * BNP + cc) = hx | (hy << 16);
        *(unsigned*)(Blo + (size_t)kr * BNP + cc) = lx | (ly << 16);
    }

    float acc[2][NT][4];
#pragma unroll
    for (int mt = 0; mt < 2; mt++)
#pragma unroll
        for (int nt = 0; nt < NT; nt++)
#pragma unroll
            for (int j = 0; j < 4; j++) acc[mt][nt][j] = 0.f;

    // A tile load mapping: thread -> (row ar, 16-col half ahalf)
    int ar = tid >> 1, ahalf = tid & 1;
    int agr = blockRow + ar;
    bool aval = agr < M;

    int lrow = lane & 15;
    int lcol8 = (lane >> 4) << 3;

#pragma unroll
    for (int kt = 0; kt < 4; kt++) {
        int k0 = kt * 32;
        // ---- load A tile (BM x 32) into smem hi/lo (convert fp32->bf16) ----
        {
            const float* ap = Asrc + (size_t)agr * 128 + k0 + ahalf * 16;
            unsigned short* dsth = Ahi + ar * AP + ahalf * 16;
            unsigned short* dstl = Alo + ar * AP + ahalf * 16;
#pragma unroll
            for (int j = 0; j < 16; j += 4) {
                float4 t;
                if (aval) t = *(const float4*)(ap + j);
                else t = make_float4(0.f, 0.f, 0.f, 0.f);
                unsigned h0 = f2bf(t.x);
                unsigned h1 = f2bf(t.y);
                unsigned h2 = f2bf(t.z);
                unsigned h3 = f2bf(t.w);
                *(unsigned*)(dsth + j)     = h0 | (h1 << 16);
                *(unsigned*)(dsth + j + 2) = h2 | (h3 << 16);
                unsigned l0 = f2bf(t.x - bf2f(h0));
                unsigned l1 = f2bf(t.y - bf2f(h1));
                unsigned l2 = f2bf(t.z - bf2f(h2));
                unsigned l3 = f2bf(t.w - bf2f(h3));
                *(unsigned*)(dstl + j)     = l0 | (l1 << 16);
                *(unsigned*)(dstl + j + 2) = l2 | (l3 << 16);
            }
        }
        __syncthreads();

#pragma unroll
        for (int ks = 0; ks < 2; ks++) {
            int kc = ks * 16;
            unsigned afh[2][4], afl[2][4];
#pragma unroll
            for (int mt = 0; mt < 2; mt++) {
                ldsm_x4(afh[mt], Ahi + (wm + mt * 16 + lrow) * AP + kc + lcol8);
                ldsm_x4(afl[mt], Alo + (wm + mt * 16 + lrow) * AP + kc + lcol8);
            }
            unsigned bfh[NT][2], bfl[NT][2];
            int krow = k0 + kc + lrow;
#pragma unroll
            for (int np = 0; np < NT / 2; np++) {
                unsigned t4[4];
                ldsm_x4t(t4, Bhi + (size_t)krow * BNP + wn + np * 16 + lcol8);
                bfh[2 * np][0] = t4[0]; bfh[2 * np][1] = t4[1];
                bfh[2 * np + 1][0] = t4[2]; bfh[2 * np + 1][1] = t4[3];
                ldsm_x4t(t4, Blo + (size_t)krow * BNP + wn + np * 16 + lcol8);
                bfl[2 * np][0] = t4[0]; bfl[2 * np][1] = t4[1];
                bfl[2 * np + 1][0] = t4[2]; bfl[2 * np + 1][1] = t4[3];
            }
#pragma unroll
            for (int mt = 0; mt < 2; mt++)
#pragma unroll
                for (int nt = 0; nt < NT; nt++) {
                    mma_bf16(acc[mt][nt], afh[mt], bfh[nt]);
                    mma_bf16(acc[mt][nt], afh[mt], bfl[nt]);
                    mma_bf16(acc[mt][nt], afl[mt], bfh[nt]);
                }
        }
        __syncthreads();
    }

    // ---- epilogue: store C + fused attention dots ----
    float ps[2][2][NH][2];
#pragma unroll
    for (int mt = 0; mt < 2; mt++)
#pragma unroll
        for (int rh = 0; rh < 2; rh++)
#pragma unroll
            for (int ih = 0; ih < NH; ih++) {
                ps[mt][rh][ih][0] = 0.f;
                ps[mt][rh][ih][1] = 0.f;
            }

#pragma unroll
    for (int mt = 0; mt < 2; mt++) {
        int row = blockRow + wm + mt * 16 + (lane >> 2);
#pragma unroll
        for (int nt = 0; nt < NT; nt++) {
            int col = wn + nt * 8 + (lane & 3) * 2;
            float c0 = acc[mt][nt][0], c1 = acc[mt][nt][1];
            float c2 = acc[mt][nt][2], c3 = acc[mt][nt][3];
            if (row < M)
                *(float2*)(C + (size_t)row * BN + col) = make_float2(c0, c1);
            if (row + 8 < M)
                *(float2*)(C + (size_t)(row + 8) * BN + col) = make_float2(c2, c3);
            float s0 = avs[col], s1 = avs[col + 1];
            float d0 = avd[col], d1 = avd[col + 1];
            int ih = (LAYER == 1) ? (nt >> 2) : 0;
            ps[mt][0][ih][0] += c0 * s0 + c1 * s1;
            ps[mt][0][ih][1] += c0 * d0 + c1 * d1;
            ps[mt][1][ih][0] += c2 * s0 + c3 * s1;
            ps[mt][1][ih][1] += c2 * d0 + c3 * d1;
        }
    }
    // reduce over the 4-lane column group
#pragma unroll
    for (int mt = 0; mt < 2; mt++)
#pragma unroll
        for (int rh = 0; rh < 2; rh++)
#pragma unroll
            for (int ih = 0; ih < NH; ih++)
#pragma unroll
                for (int sd = 0; sd < 2; sd++) {
                    float v = ps[mt][rh][ih][sd];
                    v += __shfl_xor_sync(0xffffffffu, v, 1);
                    v += __shfl_xor_sync(0xffffffffu, v, 2);
                    ps[mt][rh][ih][sd] = v;
                }
    if ((lane & 3) == 0) {
#pragma unroll
        for (int mt = 0; mt < 2; mt++)
#pragma unroll
            for (int rh = 0; rh < 2; rh++) {
                int row = blockRow + wm + mt * 16 + (lane >> 2) + rh * 8;
                if (row < M) {
                    if (LAYER == 1) {
                        int bh = wn >> 5;  // base head: 0 or 2
#pragma unroll
                        for (int ih = 0; ih < NH; ih++) {
                            g_asrc1[row * 4 + bh + ih] = ps[mt][rh][ih][0];
                            g_adst1[row * 4 + bh + ih] = ps[mt][rh][ih][1];
                        }
                    } else {
                        atomicAdd(&g_asrc2[row], ps[mt][rh][0][0]);
                        atomicAdd(&g_adst2[row], ps[mt][rh][0][1]);
                    }
                }
            }
    }
}

// ---------------- layer-1 aggregation: softmax gather (no online max) --------
// One warp per destination node. Lane l owns columns 4l..4l+3 (head = l>>3).
__global__ void k_agg1(const float* __restrict__ b1, int n) {
    int gw = (blockIdx.x * blockDim.x + threadIdx.x) >> 5;
    if (gw >= n) return;
    int lane = threadIdx.x & 31;
    int hh = lane >> 3;

    int beg = g_rowptr[gw], end = g_rowptr[gw + 1];
    float ad = g_adst1[gw * 4 + hh];
    float wd = g_wedot[hh];

    // self-loop
    float s, ax, ay, az, aw;
    {
        float alpha = g_asrc1[gw * 4 + hh] + ad + g_loopattr[gw] * wd;
        alpha = (alpha > 0.f) ? alpha : 0.2f * alpha;
        float w = __expf(alpha);
        s = w;
        float4 hv = *(const float4*)(g_h1 + (size_t)gw * 128 + lane * 4);
        ax = w * hv.x; ay = w * hv.y; az = w * hv.z; aw = w * hv.w;
    }

#pragma unroll 4
    for (int i = beg; i < end; i++) {
        int2 c = g_csr[i];
        float as = g_asrc1[c.x * 4 + hh];
        float4 hv = *(const float4*)(g_h1 + (size_t)c.x * 128 + lane * 4);
        float alpha = as + ad + __int_as_float(c.y) * wd;
        alpha = (alpha > 0.f) ? alpha : 0.2f * alpha;
        float w = __expf(alpha);
        s += w;
        ax = fmaf(w, hv.x, ax); ay = fmaf(w, hv.y, ay);
        az = fmaf(w, hv.z, az); aw = fmaf(w, hv.w, aw);
    }

    float inv = 1.f / (s + 1e-16f);
    float4 bv = *(const float4*)(b1 + lane * 4);
    float v0 = ax * inv + bv.x;
    float v1 = ay * inv + bv.y;
    float v2 = az * inv + bv.z;
    float v3 = aw * inv + bv.w;
    // ELU fused
    v0 = (v0 > 0.f) ? v0 : expm1f(v0);
    v1 = (v1 > 0.f) ? v1 : expm1f(v1);
    v2 = (v2 > 0.f) ? v2 : expm1f(v2);
    v3 = (v3 > 0.f) ? v3 : expm1f(v3);
    *(float4*)(g_h1a + (size_t)gw * 128 + lane * 4) = make_float4(v0, v1, v2, v3);
}

// ---------------- layer-2 aggregation + final FC fused (no online max) -------
__global__ void k_agg2(const float* __restrict__ b2, const float* __restrict__ fcW,
                       const float* __restrict__ fcb, float* __restrict__ out, int n) {
    int gw = (blockIdx.x * blockDim.x + threadIdx.x) >> 5;
    if (gw >= n) return;
    int lane = threadIdx.x & 31;

    int beg = g_rowptr[gw], end = g_rowptr[gw + 1];
    float ad = g_adst2[gw];
    float wd = g_wedot[4];

    float s, a0, a1;
    {
        float alpha = g_asrc2[gw] + ad + g_loopattr[gw] * wd;
        alpha = (alpha > 0.f) ? alpha : 0.2f * alpha;
        float w = __expf(alpha);
        s = w;
        float2 hv = *(const float2*)(g_h2 + (size_t)gw * 64 + lane * 2);
        a0 = w * hv.x; a1 = w * hv.y;
    }

#pragma unroll 4
    for (int i = beg; i < end; i++) {
        int2 c = g_csr[i];
        float as = g_asrc2[c.x];
        float2 hv = *(const float2*)(g_h2 + (size_t)c.x * 64 + lane * 2);
        float alpha = as + ad + __int_as_float(c.y) * wd;
        alpha = (alpha > 0.f) ? alpha : 0.2f * alpha;
        float w = __expf(alpha);
        s += w;
        a0 = fmaf(w, hv.x, a0); a1 = fmaf(w, hv.y, a1);
    }

    float inv = 1.f / (s + 1e-16f);
    float v0 = a0 * inv + b2[lane * 2];
    float v1 = a1 * inv + b2[lane * 2 + 1];
    float p = v0 * fcW[lane * 2] + v1 * fcW[lane * 2 + 1];
#pragma unroll
    for (int o = 16; o; o >>= 1) p += __shfl_xor_sync(0xffffffffu, p, o);
    if (lane == 0) out[gw] = p + fcb[0];
}

// ---------------- launch -----------------------------------------------------
extern "C" void kernel_launch(void* const* d_in, const int* in_sizes, int n_in,
                              void* d_out, int out_size) {
    const float* x    = (const float*)d_in[0];
    const int*   ei   = (const int*)d_in[1];
    const float* eatt = (const float*)d_in[2];
    const float* W1   = (const float*)d_in[3];
    const float* as1  = (const float*)d_in[4];
    const float* ad1  = (const float*)d_in[5];
    const float* We1  = (const float*)d_in[6];
    const float* ae1  = (const float*)d_in[7];
    const float* b1   = (const float*)d_in[8];
    const float* W2   = (const float*)d_in[9];
    const float* as2  = (const float*)d_in[10];
    const float* ad2  = (const float*)d_in[11];
    const float* We2  = (const float*)d_in[12];
    const float* ae2  = (const float*)d_in[13];
    const float* b2   = (const float*)d_in[14];
    const float* fcW  = (const float*)d_in[15];
    const float* fcb  = (const float*)d_in[16];
    float* out = (float*)d_out;

    int N = in_sizes[0] / 128;
    int E = in_sizes[1] / 2;
    const int* src = ei;
    const int* dst = ei + E;

    int eb = (E + 255) / 256;
    int nbscan = (N + SCAN_B - 1) / SCAN_B;
    int nwb = (N + 7) / 8;  // warp-per-node grids (8 warps / 256-thread block)

    // dynamic smem sizes for the two GEMM instantiations
    constexpr int SMEM1 = (2 * 128 * 136 + 2 * 128 * 40) * 2;  // 90112 B
    constexpr int SMEM2 = (2 * 128 * 72 + 2 * 128 * 40) * 2;   // 57344 B
    cudaFuncSetAttribute(k_gemm_mma<128, 136, false, 1>,
                         cudaFuncAttributeMaxDynamicSharedMemorySize, SMEM1);
    cudaFuncSetAttribute(k_gemm_mma<64, 72, true, 2>,
                         cudaFuncAttributeMaxDynamicSharedMemorySize, SMEM2);

    k_init<<<256, 256>>>(We1, ae1, We2, ae2, N);
    k_count<<<eb, 256>>>(dst, eatt, E);
    k_scan1<<<nbscan, SCAN_B>>>(N);
    k_scan2<<<1, 128>>>(nbscan);
    k_scan3<<<(N + 255) / 256, 256>>>(N);
    k_fill<<<eb, 256>>>(src, dst, eatt, E);

    k_gemm_mma<128, 136, false, 1><<<(N + 127) / 128, 256, SMEM1>>>(x, W1, as1, ad1, N);
    k_agg1<<<nwb, 256>>>(b1, N);

    k_gemm_mma<64, 72, true, 2><<<(N + 127) / 128, 256, SMEM2>>>(nullptr, W2, as2, ad2, N);
    k_agg2<<<nwb, 256>>>(b2, fcW, fcb, out, N);
}